// round 2
// baseline (speedup 1.0000x reference)
#include <cuda_runtime.h>
#include <cuda_bf16.h>
#include <math.h>

// ---- problem dims (compile-time capacity; runtime values read from in_sizes) ----
#define NMAX 100000
#define EMAX 1000000
#define HF   64          // hidden features
#define GMAX 256
#define NB_SCAN 128      // >= ceil(NMAX/1024)

// ---- device scratch (allocation-free rule: __device__ globals) ----
__device__ float g_h0[NMAX * HF];
__device__ float g_hA[NMAX * HF];
__device__ float g_hB[NMAX * HF];
__device__ float g_dinv[NMAX];
__device__ int   g_deg[NMAX];
__device__ int   g_roff[NMAX + 1];
__device__ int   g_cursor[NMAX];
__device__ int   g_ccol[EMAX];
__device__ float g_cw[EMAX];
__device__ float g_v[NMAX];
__device__ float g_z[GMAX * 2 * HF];
__device__ int   g_bsum[NB_SCAN];
__device__ int   g_boff[NB_SCAN];

// ---------------------------------------------------------------------------
// 1) zero deg + cursor
__global__ void k_zero(int n) {
    int i = blockIdx.x * blockDim.x + threadIdx.x;
    if (i < n) { g_deg[i] = 0; g_cursor[i] = 0; }
}

// 2) degree histogram over edge rows (edge_index[0])
__global__ void k_hist(const int* __restrict__ row, int e) {
    int i = blockIdx.x * blockDim.x + threadIdx.x;
    if (i < e) atomicAdd(&g_deg[row[i]], 1);
}

// 3) dinv = rsqrt(deg + 1)  (self-loop included; always >= 1)
__global__ void k_dinv(int n) {
    int i = blockIdx.x * blockDim.x + threadIdx.x;
    if (i < n) g_dinv[i] = rsqrtf((float)(g_deg[i] + 1));
}

// 4a) per-1024-block sums of deg
__global__ void k_scan_bsum(int n) {
    int t = threadIdx.x;
    int base = blockIdx.x * 1024;
    int s = 0;
    for (int i = t; i < 1024; i += 256) {
        int idx = base + i;
        if (idx < n) s += g_deg[idx];
    }
    __shared__ int r[256];
    r[t] = s; __syncthreads();
    for (int o = 128; o > 0; o >>= 1) {
        if (t < o) r[t] += r[t + o];
        __syncthreads();
    }
    if (t == 0) g_bsum[blockIdx.x] = r[0];
}

// 4b) exclusive scan of block sums (single block, 128 threads) + set roff[n]=E
__global__ void k_scan_part(int nb, int e, int n) {
    int t = threadIdx.x;
    __shared__ int s[NB_SCAN];
    int v = (t < nb) ? g_bsum[t] : 0;
    s[t] = v; __syncthreads();
    for (int o = 1; o < NB_SCAN; o <<= 1) {
        int u = (t >= o) ? s[t - o] : 0;
        __syncthreads();
        s[t] += u;
        __syncthreads();
    }
    g_boff[t] = s[t] - v;      // exclusive
    if (t == 0) g_roff[n] = e;
}

// 4c) final exclusive scan -> row offsets
__global__ void k_scan_final(int n) {
    int t = threadIdx.x;
    int base = blockIdx.x * 1024 + t * 4;
    int d0 = (base + 0 < n) ? g_deg[base + 0] : 0;
    int d1 = (base + 1 < n) ? g_deg[base + 1] : 0;
    int d2 = (base + 2 < n) ? g_deg[base + 2] : 0;
    int d3 = (base + 3 < n) ? g_deg[base + 3] : 0;
    int p1 = d0, p2 = d0 + d1, p3 = d0 + d1 + d2;
    int ts = p3 + d3;
    int lane = t & 31, w = t >> 5;
    int v = ts;
    #pragma unroll
    for (int o = 1; o < 32; o <<= 1) {
        int u = __shfl_up_sync(0xFFFFFFFFu, v, o);
        if (lane >= o) v += u;
    }
    __shared__ int wsum[8], woff[8];
    if (lane == 31) wsum[w] = v;
    __syncthreads();
    if (t == 0) {
        int acc = 0;
        for (int i = 0; i < 8; i++) { woff[i] = acc; acc += wsum[i]; }
    }
    __syncthreads();
    int excl = v - ts + woff[w] + g_boff[blockIdx.x];
    if (base + 0 < n) g_roff[base + 0] = excl;
    if (base + 1 < n) g_roff[base + 1] = excl + p1;
    if (base + 2 < n) g_roff[base + 2] = excl + p2;
    if (base + 3 < n) g_roff[base + 3] = excl + p3;
}

// 5) scatter edges into CSR, with precomputed edge weight dinv[r]*dinv[c]
__global__ void k_scatter(const int* __restrict__ ei, int e) {
    int i = blockIdx.x * blockDim.x + threadIdx.x;
    if (i < e) {
        int r = ei[i];
        int c = ei[e + i];
        int pos = g_roff[r] + atomicAdd(&g_cursor[r], 1);
        g_ccol[pos] = c;
        g_cw[pos] = g_dinv[r] * g_dinv[c];
    }
}

// 6) h0 = x @ W_sgc + b_sgc   (64 nodes/block, 4 threads/node x 16 features)
__global__ void k_gemm(const float* __restrict__ x, const float* __restrict__ W,
                       const float* __restrict__ b, int n) {
    __shared__ float sW[64 * 64];
    __shared__ float sx[64 * 65];
    int t = threadIdx.x;                 // 256 threads
    int base = blockIdx.x * 64;
    for (int i = t; i < 4096; i += 256) sW[i] = W[i];
    for (int i = t; i < 4096; i += 256) {
        int node = i >> 6, k = i & 63;
        int gn = base + node;
        sx[node * 65 + k] = (gn < n) ? x[gn * 64 + k] : 0.f;
    }
    __syncthreads();
    int node = t >> 2;
    int f0 = (t & 3) * 16;
    float acc[16];
    #pragma unroll
    for (int f = 0; f < 16; f++) acc[f] = b[f0 + f];
    const float* xr = &sx[node * 65];
    #pragma unroll 8
    for (int k = 0; k < 64; k++) {
        float xv = xr[k];
        const float* wr = &sW[k * 64 + f0];
        #pragma unroll
        for (int f = 0; f < 16; f++) acc[f] = fmaf(xv, wr[f], acc[f]);
    }
    int gn = base + node;
    if (gn < n) {
        float4* out = (float4*)&g_h0[gn * 64 + f0];
        out[0] = make_float4(acc[0], acc[1], acc[2], acc[3]);
        out[1] = make_float4(acc[4], acc[5], acc[6], acc[7]);
        out[2] = make_float4(acc[8], acc[9], acc[10], acc[11]);
        out[3] = make_float4(acc[12], acc[13], acc[14], acc[15]);
    }
}

// 7) one propagation hop: warp per node, float2 per lane, CSR gather (no atomics)
//    h_out = 0.5 * (sum_e w_e * h_in[col_e] + dinv^2 * h_in[i]) + 0.5 * h0
//    FINAL: fuse relu + v = sigmoid(h . w_att + b_att)
template<bool FINAL>
__global__ void k_hop(int src, const float* __restrict__ w_att,
                      const float* __restrict__ b_att, int n) {
    int wid = (blockIdx.x * blockDim.x + threadIdx.x) >> 5;
    if (wid >= n) return;
    int lane = threadIdx.x & 31;

    const float2* hin = (const float2*)(src == 0 ? g_h0 : (src == 1 ? g_hA : g_hB));
    float2* hout = (float2*)(src == 1 ? g_hB : g_hA);

    float d = g_dinv[wid];
    float ws = d * d;
    float2 hs = hin[wid * 32 + lane];
    float ax = ws * hs.x, ay = ws * hs.y;

    int s = g_roff[wid], e = g_roff[wid + 1];
    int p = s;
    for (; p + 4 <= e; p += 4) {
        int c0 = g_ccol[p], c1 = g_ccol[p + 1], c2 = g_ccol[p + 2], c3 = g_ccol[p + 3];
        float w0 = g_cw[p], w1 = g_cw[p + 1], w2 = g_cw[p + 2], w3 = g_cw[p + 3];
        float2 a0 = hin[c0 * 32 + lane];
        float2 a1 = hin[c1 * 32 + lane];
        float2 a2 = hin[c2 * 32 + lane];
        float2 a3 = hin[c3 * 32 + lane];
        ax = fmaf(w0, a0.x, ax); ay = fmaf(w0, a0.y, ay);
        ax = fmaf(w1, a1.x, ax); ay = fmaf(w1, a1.y, ay);
        ax = fmaf(w2, a2.x, ax); ay = fmaf(w2, a2.y, ay);
        ax = fmaf(w3, a3.x, ax); ay = fmaf(w3, a3.y, ay);
    }
    for (; p < e; ++p) {
        int c = g_ccol[p];
        float w = g_cw[p];
        float2 a = hin[c * 32 + lane];
        ax = fmaf(w, a.x, ax); ay = fmaf(w, a.y, ay);
    }
    float2 h0v = ((const float2*)g_h0)[wid * 32 + lane];
    float ox = 0.5f * ax + 0.5f * h0v.x;
    float oy = 0.5f * ay + 0.5f * h0v.y;

    if (FINAL) {
        ox = fmaxf(ox, 0.f);
        oy = fmaxf(oy, 0.f);
        float dp = ox * w_att[2 * lane] + oy * w_att[2 * lane + 1];
        #pragma unroll
        for (int o = 16; o > 0; o >>= 1) dp += __shfl_xor_sync(0xFFFFFFFFu, dp, o);
        if (lane == 0) g_v[wid] = 1.f / (1.f + expf(-(dp + b_att[0])));
    }
    hout[wid * 32 + lane] = make_float2(ox, oy);
}

__device__ __forceinline__ int lower_bound_i(const int* a, int n, int key) {
    int lo = 0, hi = n;
    while (lo < hi) {
        int mid = (lo + hi) >> 1;
        if (a[mid] < key) lo = mid + 1; else hi = mid;
    }
    return lo;
}

// 8) per-graph readout: segments of sorted `batch` are contiguous.
//    z[g] = [segment_max(h), segment_sum(softmax(v)*h)]
__global__ void k_readout(const int* __restrict__ batch, int n) {
    int g = blockIdx.x;
    int t = threadIdx.x;              // 128 threads
    __shared__ int sse[2];
    if (t == 0) sse[0] = lower_bound_i(batch, n, g);
    if (t == 1) sse[1] = lower_bound_i(batch, n, g + 1);
    __syncthreads();
    int s = sse[0], e = sse[1];

    __shared__ float red[128];
    // vmax
    float lm = -INFINITY;
    for (int i = s + t; i < e; i += 128) lm = fmaxf(lm, g_v[i]);
    red[t] = lm; __syncthreads();
    for (int o = 64; o > 0; o >>= 1) { if (t < o) red[t] = fmaxf(red[t], red[t + o]); __syncthreads(); }
    float vmax = red[0];
    __syncthreads();
    // vsum
    float ls = 0.f;
    for (int i = s + t; i < e; i += 128) ls += expf(g_v[i] - vmax);
    red[t] = ls; __syncthreads();
    for (int o = 64; o > 0; o >>= 1) { if (t < o) red[t] += red[t + o]; __syncthreads(); }
    float inv = 1.f / (red[0] + 1e-16f);
    __syncthreads();

    int f = t & 63, half = t >> 6;
    float gmax = -INFINITY, gsum = 0.f;
    for (int i = s + half; i < e; i += 2) {
        float ev = expf(g_v[i] - vmax);
        float hv = g_hA[i * 64 + f];
        gmax = fmaxf(gmax, hv);
        gsum = fmaf(ev, hv, gsum);
    }
    __shared__ float smax[64], ssum[64];
    if (half == 0) { smax[f] = gmax; ssum[f] = gsum; }
    __syncthreads();
    if (half == 1) { smax[f] = fmaxf(smax[f], gmax); ssum[f] += gsum; }
    __syncthreads();
    if (t < 64) {
        g_z[g * 128 + t]      = smax[t];
        g_z[g * 128 + 64 + t] = ssum[t] * inv;
    }
}

// 9) MLP head + log_softmax (one block of 64 threads per graph)
__global__ void k_mlp(const float* __restrict__ W1, const float* __restrict__ b1,
                      const float* __restrict__ W2, const float* __restrict__ b2,
                      const float* __restrict__ W3, const float* __restrict__ b3,
                      float* __restrict__ out) {
    int g = blockIdx.x, t = threadIdx.x;   // 64 threads
    __shared__ float sz[128], s1[64], s2[32], s3[8], lse;
    sz[t] = g_z[g * 128 + t];
    sz[t + 64] = g_z[g * 128 + 64 + t];
    __syncthreads();
    float a = b1[t];
    #pragma unroll 8
    for (int k = 0; k < 128; k++) a = fmaf(sz[k], W1[k * 64 + t], a);
    s1[t] = fmaxf(a, 0.f);
    __syncthreads();
    if (t < 32) {
        float a2 = b2[t];
        #pragma unroll 8
        for (int k = 0; k < 64; k++) a2 = fmaf(s1[k], W2[k * 32 + t], a2);
        s2[t] = fmaxf(a2, 0.f);
    }
    __syncthreads();
    if (t < 8) {
        float a3 = b3[t];
        #pragma unroll
        for (int k = 0; k < 32; k++) a3 = fmaf(s2[k], W3[k * 8 + t], a3);
        s3[t] = a3;
    }
    __syncthreads();
    if (t == 0) {
        float m = s3[0];
        for (int c = 1; c < 8; c++) m = fmaxf(m, s3[c]);
        float ss = 0.f;
        for (int c = 0; c < 8; c++) ss += expf(s3[c] - m);
        lse = m + logf(ss);
    }
    __syncthreads();
    if (t < 8) out[g * 8 + t] = s3[t] - lse;
}

extern "C" void kernel_launch(void* const* d_in, const int* in_sizes, int n_in,
                              void* d_out, int out_size) {
    const float* x     = (const float*)d_in[0];
    const int*   ei    = (const int*)  d_in[1];   // [2, E] flattened
    const int*   batch = (const int*)  d_in[2];
    const float* W_sgc = (const float*)d_in[3];
    const float* b_sgc = (const float*)d_in[4];
    const float* w_att = (const float*)d_in[5];
    const float* b_att = (const float*)d_in[6];
    const float* W1    = (const float*)d_in[7];
    const float* b1    = (const float*)d_in[8];
    const float* W2    = (const float*)d_in[9];
    const float* b2    = (const float*)d_in[10];
    const float* W3    = (const float*)d_in[11];
    const float* b3    = (const float*)d_in[12];
    float* out = (float*)d_out;

    int n = in_sizes[0] / HF;        // nodes
    int e = in_sizes[1] / 2;         // edges
    int g = out_size / 8;            // graphs

    int nb = (n + 1023) / 1024;      // scan blocks

    k_zero<<<(n + 255) / 256, 256>>>(n);
    k_hist<<<(e + 255) / 256, 256>>>(ei, e);
    k_dinv<<<(n + 255) / 256, 256>>>(n);
    k_scan_bsum<<<nb, 256>>>(n);
    k_scan_part<<<1, NB_SCAN>>>(nb, e, n);
    k_scan_final<<<nb, 256>>>(n);
    k_scatter<<<(e + 255) / 256, 256>>>(ei, e);

    k_gemm<<<(n + 63) / 64, 256>>>(x, W_sgc, b_sgc, n);

    int hop_blocks = (n * 32 + 255) / 256;
    k_hop<false><<<hop_blocks, 256>>>(0, w_att, b_att, n);   // h0 -> hA
    k_hop<false><<<hop_blocks, 256>>>(1, w_att, b_att, n);   // hA -> hB
    k_hop<true ><<<hop_blocks, 256>>>(2, w_att, b_att, n);   // hB -> hA (+relu +v)

    k_readout<<<g, 128>>>(batch, n);
    k_mlp<<<g, 64>>>(W1, b1, W2, b2, W3, b3, out);
}

// round 3
// speedup vs baseline: 1.4076x; 1.4076x over previous
#include <cuda_runtime.h>
#include <cuda_bf16.h>
#include <math.h>

// ---- problem dims (compile-time capacity; runtime values read from in_sizes) ----
#define NMAX 100000
#define EMAX 1000000
#define HF   64          // hidden features
#define GMAX 256
#define NB_SCAN 128      // >= ceil(NMAX/1024)

// ---- device scratch (allocation-free rule: __device__ globals) ----
__device__ float g_h0[NMAX * HF];
__device__ float g_hA[NMAX * HF];
__device__ float g_hB[NMAX * HF];
__device__ float g_dinv[NMAX];
__device__ int   g_deg[NMAX];
__device__ int   g_roff[NMAX + 1];
__device__ int   g_cursor[NMAX];
__device__ int   g_ccol[EMAX];
__device__ float g_cw[EMAX];
__device__ float g_v[NMAX];
__device__ float g_z[GMAX * 2 * HF];
__device__ int   g_bsum[NB_SCAN];
__device__ int   g_boff[NB_SCAN];

// ---------------------------------------------------------------------------
// 1) zero deg (int4 vectorized; 1024 ints per block)
__global__ void k_zero(int n) {
    int i4 = blockIdx.x * blockDim.x + threadIdx.x;
    int base = i4 * 4;
    if (base + 3 < n) {
        ((int4*)g_deg)[i4] = make_int4(0, 0, 0, 0);
    } else {
        for (int j = base; j < n; j++) g_deg[j] = 0;
    }
}

// 2) degree histogram over edge rows (int4 loads, 4 atomics/thread)
__global__ void k_hist(const int* __restrict__ row, int e) {
    int i = blockIdx.x * blockDim.x + threadIdx.x;
    int base = i * 4;
    if (base + 3 < e) {
        int4 r = ((const int4*)row)[i];
        atomicAdd(&g_deg[r.x], 1);
        atomicAdd(&g_deg[r.y], 1);
        atomicAdd(&g_deg[r.z], 1);
        atomicAdd(&g_deg[r.w], 1);
    } else {
        for (int j = base; j < e; j++) atomicAdd(&g_deg[row[j]], 1);
    }
}

// 3) per-1024-block sums of deg (int4) + fused dinv computation
__global__ void k_scan_bsum(int n) {
    int t = threadIdx.x;                  // 256
    int i4 = blockIdx.x * 256 + t;
    int base = i4 * 4;
    int s = 0;
    if (base + 3 < n) {
        int4 d = ((const int4*)g_deg)[i4];
        s = d.x + d.y + d.z + d.w;
        float4 di;
        di.x = rsqrtf((float)(d.x + 1));
        di.y = rsqrtf((float)(d.y + 1));
        di.z = rsqrtf((float)(d.z + 1));
        di.w = rsqrtf((float)(d.w + 1));
        ((float4*)g_dinv)[i4] = di;
    } else {
        for (int j = base; j < n; j++) {
            int d = g_deg[j];
            s += d;
            g_dinv[j] = rsqrtf((float)(d + 1));
        }
    }
    // warp reduce then smem
    #pragma unroll
    for (int o = 16; o > 0; o >>= 1) s += __shfl_xor_sync(0xFFFFFFFFu, s, o);
    __shared__ int r[8];
    if ((t & 31) == 0) r[t >> 5] = s;
    __syncthreads();
    if (t == 0) {
        int acc = 0;
        #pragma unroll
        for (int i = 0; i < 8; i++) acc += r[i];
        g_bsum[blockIdx.x] = acc;
    }
}

// 4) exclusive scan of block sums (single block) + set roff[n]=E
__global__ void k_scan_part(int nb, int e, int n) {
    int t = threadIdx.x;
    __shared__ int s[NB_SCAN];
    int v = (t < nb) ? g_bsum[t] : 0;
    s[t] = v; __syncthreads();
    for (int o = 1; o < NB_SCAN; o <<= 1) {
        int u = (t >= o) ? s[t - o] : 0;
        __syncthreads();
        s[t] += u;
        __syncthreads();
    }
    g_boff[t] = s[t] - v;      // exclusive
    if (t == 0) g_roff[n] = e;
}

// 5) final exclusive scan -> row offsets; also zero cursor
__global__ void k_scan_final(int n) {
    int t = threadIdx.x;
    int base = blockIdx.x * 1024 + t * 4;
    int d0 = (base + 0 < n) ? g_deg[base + 0] : 0;
    int d1 = (base + 1 < n) ? g_deg[base + 1] : 0;
    int d2 = (base + 2 < n) ? g_deg[base + 2] : 0;
    int d3 = (base + 3 < n) ? g_deg[base + 3] : 0;
    int p1 = d0, p2 = d0 + d1, p3 = d0 + d1 + d2;
    int ts = p3 + d3;
    int lane = t & 31, w = t >> 5;
    int v = ts;
    #pragma unroll
    for (int o = 1; o < 32; o <<= 1) {
        int u = __shfl_up_sync(0xFFFFFFFFu, v, o);
        if (lane >= o) v += u;
    }
    __shared__ int wsum[8], woff[8];
    if (lane == 31) wsum[w] = v;
    __syncthreads();
    if (t == 0) {
        int acc = 0;
        for (int i = 0; i < 8; i++) { woff[i] = acc; acc += wsum[i]; }
    }
    __syncthreads();
    int excl = v - ts + woff[w] + g_boff[blockIdx.x];
    if (base + 0 < n) { g_roff[base + 0] = excl;      g_cursor[base + 0] = 0; }
    if (base + 1 < n) { g_roff[base + 1] = excl + p1; g_cursor[base + 1] = 0; }
    if (base + 2 < n) { g_roff[base + 2] = excl + p2; g_cursor[base + 2] = 0; }
    if (base + 3 < n) { g_roff[base + 3] = excl + p3; g_cursor[base + 3] = 0; }
}

// 6) scatter edges into CSR, with precomputed edge weight dinv[r]*dinv[c]
__global__ void k_scatter(const int* __restrict__ ei, int e) {
    int i = blockIdx.x * blockDim.x + threadIdx.x;
    if (i < e) {
        int r = ei[i];
        int c = ei[e + i];
        int pos = g_roff[r] + atomicAdd(&g_cursor[r], 1);
        g_ccol[pos] = c;
        g_cw[pos] = g_dinv[r] * g_dinv[c];
    }
}

// 7) h0 = x @ W_sgc + b_sgc   -- 128-node tile, 8x8 register blocking, 128 thr
__global__ void __launch_bounds__(128) k_gemm(
        const float* __restrict__ x, const float* __restrict__ W,
        const float* __restrict__ b, int n) {
    __shared__ float sxT[64][132];     // x transposed: [k][node], padded
    __shared__ float sW[64 * 64];      // W row-major [k][f]
    int t = threadIdx.x;               // 128 threads
    int base = blockIdx.x * 128;

    // load W (4096 floats, float4)
    for (int i = t * 4; i < 4096; i += 512)
        *(float4*)&sW[i] = *(const float4*)&W[i];

    // load x transposed: thread t owns node base+t
    int gn = base + t;
    if (gn < n) {
        #pragma unroll
        for (int k = 0; k < 64; k += 4) {
            float4 v = *(const float4*)&x[gn * 64 + k];
            sxT[k + 0][t] = v.x;
            sxT[k + 1][t] = v.y;
            sxT[k + 2][t] = v.z;
            sxT[k + 3][t] = v.w;
        }
    } else {
        #pragma unroll
        for (int k = 0; k < 64; k++) sxT[k][t] = 0.f;
    }
    __syncthreads();

    int tx = t & 7, ty = t >> 3;       // 8 feature-groups x 16 node-groups
    int f0 = tx * 8, n0 = ty * 8;
    float acc[8][8];
    #pragma unroll
    for (int j = 0; j < 8; j++) {
        float bj = b[f0 + j];
        #pragma unroll
        for (int i = 0; i < 8; i++) acc[i][j] = bj;
    }
    #pragma unroll 4
    for (int k = 0; k < 64; k++) {
        float a[8], bb[8];
        *(float4*)&a[0]  = *(float4*)&sxT[k][n0];
        *(float4*)&a[4]  = *(float4*)&sxT[k][n0 + 4];
        *(float4*)&bb[0] = *(float4*)&sW[k * 64 + f0];
        *(float4*)&bb[4] = *(float4*)&sW[k * 64 + f0 + 4];
        #pragma unroll
        for (int i = 0; i < 8; i++)
            #pragma unroll
            for (int j = 0; j < 8; j++)
                acc[i][j] = fmaf(a[i], bb[j], acc[i][j]);
    }
    #pragma unroll
    for (int i = 0; i < 8; i++) {
        int gnode = base + n0 + i;
        if (gnode < n) {
            float4* out = (float4*)&g_h0[gnode * 64 + f0];
            out[0] = make_float4(acc[i][0], acc[i][1], acc[i][2], acc[i][3]);
            out[1] = make_float4(acc[i][4], acc[i][5], acc[i][6], acc[i][7]);
        }
    }
}

// 8) one propagation hop: warp per node, HALF-WARP per edge (float4 x 16 lanes
//    = 256B row), 2 edges in flight per step, 4 per unrolled iter.
//    h_out = 0.5 * (sum_e w_e * h_in[col_e] + dinv^2 * h_in[i]) + 0.5 * h0
//    FINAL: fuse relu + v = sigmoid(h . w_att + b_att)
template<int SRC, bool FINAL>
__global__ void __launch_bounds__(256) k_hop(const float* __restrict__ w_att,
                                             const float* __restrict__ b_att,
                                             int n) {
    int wid = (blockIdx.x * blockDim.x + threadIdx.x) >> 5;
    if (wid >= n) return;
    int lane = threadIdx.x & 31;
    int half = lane >> 4, hl = lane & 15;

    const float4* hin = (const float4*)(SRC == 0 ? g_h0 : (SRC == 1 ? g_hA : g_hB));
    float4* hout = (float4*)(SRC == 1 ? g_hB : g_hA);

    float d = g_dinv[wid];
    float ws = d * d;
    float4 hs = hin[wid * 16 + hl];          // self row (all lanes, bcast per half)

    float4 acc = make_float4(0.f, 0.f, 0.f, 0.f);
    int s = g_roff[wid], e = g_roff[wid + 1];
    int p = s;
    for (; p + 4 <= e; p += 4) {
        int   c0 = g_ccol[p + half];
        float w0 = g_cw[p + half];
        int   c1 = g_ccol[p + 2 + half];
        float w1 = g_cw[p + 2 + half];
        float4 a0 = hin[c0 * 16 + hl];
        float4 a1 = hin[c1 * 16 + hl];
        acc.x = fmaf(w0, a0.x, acc.x); acc.y = fmaf(w0, a0.y, acc.y);
        acc.z = fmaf(w0, a0.z, acc.z); acc.w = fmaf(w0, a0.w, acc.w);
        acc.x = fmaf(w1, a1.x, acc.x); acc.y = fmaf(w1, a1.y, acc.y);
        acc.z = fmaf(w1, a1.z, acc.z); acc.w = fmaf(w1, a1.w, acc.w);
    }
    if (p + 2 <= e) {
        int   c = g_ccol[p + half];
        float w = g_cw[p + half];
        float4 a = hin[c * 16 + hl];
        acc.x = fmaf(w, a.x, acc.x); acc.y = fmaf(w, a.y, acc.y);
        acc.z = fmaf(w, a.z, acc.z); acc.w = fmaf(w, a.w, acc.w);
        p += 2;
    }
    if (p < e) {   // odd remainder: half 0 carries the weight, half 1 adds 0
        int   c = g_ccol[p];
        float w = half ? 0.f : g_cw[p];
        float4 a = hin[c * 16 + hl];
        acc.x = fmaf(w, a.x, acc.x); acc.y = fmaf(w, a.y, acc.y);
        acc.z = fmaf(w, a.z, acc.z); acc.w = fmaf(w, a.w, acc.w);
    }
    // combine the two half-warps (same feature slots)
    acc.x += __shfl_xor_sync(0xFFFFFFFFu, acc.x, 16);
    acc.y += __shfl_xor_sync(0xFFFFFFFFu, acc.y, 16);
    acc.z += __shfl_xor_sync(0xFFFFFFFFu, acc.z, 16);
    acc.w += __shfl_xor_sync(0xFFFFFFFFu, acc.w, 16);

    float4 h0v;
    if (SRC == 0) h0v = hs;                                    // hin IS h0
    else          h0v = ((const float4*)g_h0)[wid * 16 + hl];

    float4 o;
    o.x = 0.5f * (acc.x + ws * hs.x) + 0.5f * h0v.x;
    o.y = 0.5f * (acc.y + ws * hs.y) + 0.5f * h0v.y;
    o.z = 0.5f * (acc.z + ws * hs.z) + 0.5f * h0v.z;
    o.w = 0.5f * (acc.w + ws * hs.w) + 0.5f * h0v.w;

    if (FINAL) {
        o.x = fmaxf(o.x, 0.f); o.y = fmaxf(o.y, 0.f);
        o.z = fmaxf(o.z, 0.f); o.w = fmaxf(o.w, 0.f);
        float4 wa = ((const float4*)w_att)[hl];
        float dp = o.x * wa.x + o.y * wa.y + o.z * wa.z + o.w * wa.w;
        #pragma unroll
        for (int off = 8; off > 0; off >>= 1)
            dp += __shfl_xor_sync(0xFFFFFFFFu, dp, off);
        if (lane == 0) g_v[wid] = 1.f / (1.f + expf(-(dp + b_att[0])));
    }
    if (half == 0) hout[wid * 16 + hl] = o;
}

__device__ __forceinline__ int lower_bound_i(const int* a, int n, int key) {
    int lo = 0, hi = n;
    while (lo < hi) {
        int mid = (lo + hi) >> 1;
        if (a[mid] < key) lo = mid + 1; else hi = mid;
    }
    return lo;
}

// 9) per-graph readout: segments of sorted `batch` are contiguous.
//    z[g] = [segment_max(h), segment_sum(softmax(v)*h)]
__global__ void __launch_bounds__(128) k_readout(const int* __restrict__ batch, int n) {
    int g = blockIdx.x;
    int t = threadIdx.x;              // 128 threads
    __shared__ int sse[2];
    if (t == 0) sse[0] = lower_bound_i(batch, n, g);
    if (t == 1) sse[1] = lower_bound_i(batch, n, g + 1);
    __syncthreads();
    int s = sse[0], e = sse[1];

    __shared__ float red[128];
    // vmax
    float lm = -INFINITY;
    for (int i = s + t; i < e; i += 128) lm = fmaxf(lm, g_v[i]);
    red[t] = lm; __syncthreads();
    for (int o = 64; o > 0; o >>= 1) { if (t < o) red[t] = fmaxf(red[t], red[t + o]); __syncthreads(); }
    float vmax = red[0];
    __syncthreads();
    // vsum
    float ls = 0.f;
    for (int i = s + t; i < e; i += 128) ls += expf(g_v[i] - vmax);
    red[t] = ls; __syncthreads();
    for (int o = 64; o > 0; o >>= 1) { if (t < o) red[t] += red[t + o]; __syncthreads(); }
    float inv = 1.f / (red[0] + 1e-16f);
    __syncthreads();

    // pooled stats: 8 row-walkers x 16 feature lanes (float4 each)
    int hl = t & 15, r8 = t >> 4;
    const float4* h4 = (const float4*)g_hA;
    float4 gmax = make_float4(-INFINITY, -INFINITY, -INFINITY, -INFINITY);
    float4 gsum = make_float4(0.f, 0.f, 0.f, 0.f);
    for (int i = s + r8; i < e; i += 8) {
        float ev = expf(g_v[i] - vmax);
        float4 hv = h4[i * 16 + hl];
        gmax.x = fmaxf(gmax.x, hv.x); gmax.y = fmaxf(gmax.y, hv.y);
        gmax.z = fmaxf(gmax.z, hv.z); gmax.w = fmaxf(gmax.w, hv.w);
        gsum.x = fmaf(ev, hv.x, gsum.x); gsum.y = fmaf(ev, hv.y, gsum.y);
        gsum.z = fmaf(ev, hv.z, gsum.z); gsum.w = fmaf(ev, hv.w, gsum.w);
    }
    __shared__ float4 smax[128], ssum[128];
    smax[t] = gmax; ssum[t] = gsum;
    __syncthreads();
    if (r8 == 0) {
        #pragma unroll
        for (int j = 1; j < 8; j++) {
            float4 m = smax[hl + 16 * j], sv = ssum[hl + 16 * j];
            gmax.x = fmaxf(gmax.x, m.x); gmax.y = fmaxf(gmax.y, m.y);
            gmax.z = fmaxf(gmax.z, m.z); gmax.w = fmaxf(gmax.w, m.w);
            gsum.x += sv.x; gsum.y += sv.y; gsum.z += sv.z; gsum.w += sv.w;
        }
        ((float4*)&g_z[g * 128])[hl] = gmax;
        gsum.x *= inv; gsum.y *= inv; gsum.z *= inv; gsum.w *= inv;
        ((float4*)&g_z[g * 128 + 64])[hl] = gsum;
    }
}

// 10) MLP head + log_softmax (one block of 64 threads per graph)
__global__ void k_mlp(const float* __restrict__ W1, const float* __restrict__ b1,
                      const float* __restrict__ W2, const float* __restrict__ b2,
                      const float* __restrict__ W3, const float* __restrict__ b3,
                      float* __restrict__ out) {
    int g = blockIdx.x, t = threadIdx.x;   // 64 threads
    __shared__ float sz[128], s1[64], s2[32], s3[8], lse;
    sz[t] = g_z[g * 128 + t];
    sz[t + 64] = g_z[g * 128 + 64 + t];
    __syncthreads();
    float a = b1[t];
    #pragma unroll 8
    for (int k = 0; k < 128; k++) a = fmaf(sz[k], W1[k * 64 + t], a);
    s1[t] = fmaxf(a, 0.f);
    __syncthreads();
    if (t < 32) {
        float a2 = b2[t];
        #pragma unroll 8
        for (int k = 0; k < 64; k++) a2 = fmaf(s1[k], W2[k * 32 + t], a2);
        s2[t] = fmaxf(a2, 0.f);
    }
    __syncthreads();
    if (t < 8) {
        float a3 = b3[t];
        #pragma unroll
        for (int k = 0; k < 32; k++) a3 = fmaf(s2[k], W3[k * 8 + t], a3);
        s3[t] = a3;
    }
    __syncthreads();
    if (t == 0) {
        float m = s3[0];
        for (int c = 1; c < 8; c++) m = fmaxf(m, s3[c]);
        float ss = 0.f;
        for (int c = 0; c < 8; c++) ss += expf(s3[c] - m);
        lse = m + logf(ss);
    }
    __syncthreads();
    if (t < 8) out[g * 8 + t] = s3[t] - lse;
}

extern "C" void kernel_launch(void* const* d_in, const int* in_sizes, int n_in,
                              void* d_out, int out_size) {
    const float* x     = (const float*)d_in[0];
    const int*   ei    = (const int*)  d_in[1];   // [2, E] flattened
    const int*   batch = (const int*)  d_in[2];
    const float* W_sgc = (const float*)d_in[3];
    const float* b_sgc = (const float*)d_in[4];
    const float* w_att = (const float*)d_in[5];
    const float* b_att = (const float*)d_in[6];
    const float* W1    = (const float*)d_in[7];
    const float* b1    = (const float*)d_in[8];
    const float* W2    = (const float*)d_in[9];
    const float* b2    = (const float*)d_in[10];
    const float* W3    = (const float*)d_in[11];
    const float* b3    = (const float*)d_in[12];
    float* out = (float*)d_out;

    int n = in_sizes[0] / HF;        // nodes
    int e = in_sizes[1] / 2;         // edges
    int g = out_size / 8;            // graphs

    int nb = (n + 1023) / 1024;      // 1024-element scan blocks

    k_zero<<<nb, 256>>>(n);
    k_hist<<<(e / 4 + 255) / 256 + 1, 256>>>(ei, e);
    k_scan_bsum<<<nb, 256>>>(n);
    k_scan_part<<<1, NB_SCAN>>>(nb, e, n);
    k_scan_final<<<nb, 256>>>(n);
    k_scatter<<<(e + 255) / 256, 256>>>(ei, e);

    k_gemm<<<(n + 127) / 128, 128>>>(x, W_sgc, b_sgc, n);

    int hop_blocks = (n * 32 + 255) / 256;
    k_hop<0, false><<<hop_blocks, 256>>>(w_att, b_att, n);   // h0 -> hA
    k_hop<1, false><<<hop_blocks, 256>>>(w_att, b_att, n);   // hA -> hB
    k_hop<2, true ><<<hop_blocks, 256>>>(w_att, b_att, n);   // hB -> hA (+relu +v)

    k_readout<<<g, 128>>>(batch, n);
    k_mlp<<<g, 64>>>(W1, b1, W2, b2, W3, b3, out);
}